// round 2
// baseline (speedup 1.0000x reference)
#include <cuda_runtime.h>
#include <cuda_bf16.h>

#define OUTSZ 224
#define NBINS 8
#define FW 512
#define FH 512
#define TPB 256

__global__ __launch_bounds__(TPB)
void vel_hist_kernel(const float* __restrict__ flows,
                     const float* __restrict__ boxes,
                     float* __restrict__ out)
{
    // packed per-axis params: col: {x0(int), x1(int), fx, mask}; row: {ry0(int), ry1(int), fy, mask}
    __shared__ float4 s_col[OUTSZ];
    __shared__ float4 s_row[OUTSZ];
    __shared__ float hsum[NBINS * TPB];
    __shared__ float hcnt[NBINS * TPB];

    const int box = blockIdx.x;
    const int tid = threadIdx.x;

    const float bf  = boxes[box * 5 + 0];
    const float bx1 = boxes[box * 5 + 1];
    const float by1 = boxes[box * 5 + 2];
    const float bx2 = boxes[box * 5 + 3];
    const float by2 = boxes[box * 5 + 4];
    const int bidx = (int)bf;
    const float roi_w = fmaxf(bx2 - bx1, 1.0f);
    const float roi_h = fmaxf(by2 - by1, 1.0f);

    if (tid < OUTSZ) {
        float g = ((float)tid + 0.5f) / (float)OUTSZ;
        // x axis
        float px = bx1 + g * roi_w;
        float mx = (px >= -1.0f && px <= (float)FW) ? 1.0f : 0.0f;
        float pcx = fminf(fmaxf(px, 0.0f), (float)(FW - 1));
        int xl = (int)floorf(pcx);
        int xh = min(xl + 1, FW - 1);
        s_col[tid] = make_float4(__int_as_float(xl), __int_as_float(xh),
                                 pcx - (float)xl, mx);
        // y axis
        float py = by1 + g * roi_h;
        float my = (py >= -1.0f && py <= (float)FH) ? 1.0f : 0.0f;
        float pcy = fminf(fmaxf(py, 0.0f), (float)(FH - 1));
        int yl = (int)floorf(pcy);
        int yh = min(yl + 1, FH - 1);
        s_row[tid] = make_float4(__int_as_float(yl * FW), __int_as_float(yh * FW),
                                 pcy - (float)yl, my);
    }
#pragma unroll
    for (int b = 0; b < NBINS; b++) {
        hsum[b * TPB + tid] = 0.0f;
        hcnt[b * TPB + tid] = 0.0f;
    }
    __syncthreads();

    const float* __restrict__ c0 = flows + (size_t)bidx * 2u * FH * FW;
    const float* __restrict__ c1 = c0 + FH * FW;
    float* msum = hsum + tid;
    float* mcnt = hcnt + tid;

    const int ITERS = (OUTSZ * OUTSZ) / TPB;   // 196, exact
#pragma unroll 2
    for (int k = 0; k < ITERS; k++) {
        int s = tid + (k << 8);
        int i = s / OUTSZ;
        int j = s - i * OUTSZ;

        float4 cp = s_col[j];
        float4 rp = s_row[i];
        int xa = __float_as_int(cp.x), xb = __float_as_int(cp.y);
        float fx = cp.z, mxx = cp.w;
        int r0 = __float_as_int(rp.x), r1 = __float_as_int(rp.y);
        float fy = rp.z, myy = rp.w;

        float gx = 1.0f - fx, gy = 1.0f - fy;
        float w00 = gy * gx, w01 = gy * fx, w10 = fy * gx, w11 = fy * fx;
        int o00 = r0 + xa, o01 = r0 + xb, o10 = r1 + xa, o11 = r1 + xb;

        float a = w00 * __ldg(c0 + o00) + w01 * __ldg(c0 + o01)
                + w10 * __ldg(c0 + o10) + w11 * __ldg(c0 + o11);
        float b = w00 * __ldg(c1 + o00) + w01 * __ldg(c1 + o01)
                + w10 * __ldg(c1 + o10) + w11 * __ldg(c1 + o11);

        // masked samples become exactly +0.0f (select, NOT multiply: 0*-x = -0,
        // and atan2(-0, b<0) = -pi would land in bin 0 instead of reference's bin 4)
        bool valid = (mxx != 0.0f) && (myy != 0.0f);
        a = valid ? a : 0.0f;
        b = valid ? b : 0.0f;

        float mag = sqrtf(a * a + b * b);

        // bin = floor((atan2(a,b)+pi) * 8/(2*pi)), clipped to [0,7] => octant of (b,a)
        int bin;
        if (a > 0.0f) {
            if (b > 0.0f)      bin = (a < b)   ? 4 : 5;   // [0,pi/4) -> 4 ; [pi/4,pi/2) -> 5
            else if (b < 0.0f) bin = (a > -b)  ? 6 : 7;   // (pi/2,3pi/4) -> 6 ; [3pi/4,pi) -> 7
            else               bin = 6;                   // theta = pi/2
        } else if (a < 0.0f) {
            if (b > 0.0f)      bin = (-a <= b) ? 3 : 2;   // [-pi/4,0) -> 3 ; (-pi/2,-pi/4) -> 2
            else if (b < 0.0f) bin = (a > b)   ? 0 : 1;   // [-pi,-3pi/4) -> 0 ; [-3pi/4,-pi/2) -> 1
            else               bin = 2;                   // theta = -pi/2
        } else {
            bin = (b < 0.0f) ? 7 : 4;                     // theta = pi -> clip 7 ; theta = 0 (incl. 0,0) -> 4
        }

        msum[bin << 8] += mag;
        mcnt[bin << 8] += 1.0f;
    }
    __syncthreads();

    // 8 warps reduce 8 bins (warp w -> bin w), 256 partials each
    int wid = tid >> 5, lane = tid & 31;
    float s = 0.0f, c = 0.0f;
#pragma unroll
    for (int t = 0; t < TPB; t += 32) {
        s += hsum[(wid << 8) + lane + t];
        c += hcnt[(wid << 8) + lane + t];
    }
#pragma unroll
    for (int d = 16; d > 0; d >>= 1) {
        s += __shfl_down_sync(0xffffffffu, s, d);
        c += __shfl_down_sync(0xffffffffu, c, d);
    }
    if (lane == 0) {
        out[box * NBINS + wid] = (c != 0.0f) ? (s / c) : 0.0f;
    }
}

extern "C" void kernel_launch(void* const* d_in, const int* in_sizes, int n_in,
                              void* d_out, int out_size) {
    const float* flows = (const float*)d_in[0];   // (8, 2, 512, 512) f32
    const float* boxes = (const float*)d_in[1];   // (512, 5) f32
    float* out = (float*)d_out;                   // (512, 8) f32
    int M = in_sizes[1] / 5;
    vel_hist_kernel<<<M, TPB>>>(flows, boxes, out);
}

// round 3
// speedup vs baseline: 1.2101x; 1.2101x over previous
#include <cuda_runtime.h>
#include <cuda_bf16.h>

#define OUTSZ 224
#define NBINS 8
#define FW 512
#define FH 512
#define TPB 256
#define SPLIT 4                     // CTAs per box
#define ITERS_TOTAL ((OUTSZ * OUTSZ) / TPB)   // 196
#define ITERS_PART (ITERS_TOTAL / SPLIT)      // 49  (per-thread per-bin count <= 49 < 256 -> 8-bit fields OK)
#define NBOX 512

// partial results: [box*SPLIT + part][bin]
__device__ float g_psum[NBOX * SPLIT * NBINS];
__device__ float g_pcnt[NBOX * SPLIT * NBINS];

__global__ __launch_bounds__(TPB)
void vel_hist_part_kernel(const float* __restrict__ flows,
                          const float* __restrict__ boxes)
{
    __shared__ float4 s_col[OUTSZ];
    __shared__ float4 s_row[OUTSZ];
    __shared__ float hsum[NBINS * TPB];
    __shared__ float hcnt[NBINS * TPB];

    const int bx   = blockIdx.x;
    const int box  = bx >> 2;          // SPLIT = 4
    const int part = bx & 3;
    const int tid  = threadIdx.x;

    const float bf  = boxes[box * 5 + 0];
    const float bx1 = boxes[box * 5 + 1];
    const float by1 = boxes[box * 5 + 2];
    const float bx2 = boxes[box * 5 + 3];
    const float by2 = boxes[box * 5 + 4];
    const int bidx = (int)bf;
    const float roi_w = fmaxf(bx2 - bx1, 1.0f);
    const float roi_h = fmaxf(by2 - by1, 1.0f);

    if (tid < OUTSZ) {
        float g = ((float)tid + 0.5f) / (float)OUTSZ;
        // x axis
        float px = bx1 + g * roi_w;
        float mx = (px >= -1.0f && px <= (float)FW) ? 1.0f : 0.0f;
        float pcx = fminf(fmaxf(px, 0.0f), (float)(FW - 1));
        int xl = (int)floorf(pcx);
        int xh = min(xl + 1, FW - 1);
        s_col[tid] = make_float4(__int_as_float(xl), __int_as_float(xh),
                                 pcx - (float)xl, mx);
        // y axis
        float py = by1 + g * roi_h;
        float my = (py >= -1.0f && py <= (float)FH) ? 1.0f : 0.0f;
        float pcy = fminf(fmaxf(py, 0.0f), (float)(FH - 1));
        int yl = (int)floorf(pcy);
        int yh = min(yl + 1, FH - 1);
        s_row[tid] = make_float4(__int_as_float(yl * FW), __int_as_float(yh * FW),
                                 pcy - (float)yl, my);
    }
#pragma unroll
    for (int b = 0; b < NBINS; b++)
        hsum[b * TPB + tid] = 0.0f;
    __syncthreads();

    const float* __restrict__ c0 = flows + (size_t)bidx * 2u * FH * FW;
    const float* __restrict__ c1 = c0 + FH * FW;
    float* msum = hsum + tid;

    unsigned int cnt0 = 0u, cnt1 = 0u;   // 8 packed 8-bit counters (bins 0-3, 4-7)
    const int sbase = part * (ITERS_PART * TPB) + tid;

#pragma unroll 2
    for (int k = 0; k < ITERS_PART; k++) {
        int s = sbase + (k << 8);
        int i = s / OUTSZ;
        int j = s - i * OUTSZ;

        float4 cp = s_col[j];
        float4 rp = s_row[i];
        int xa = __float_as_int(cp.x), xb = __float_as_int(cp.y);
        float fx = cp.z, mxx = cp.w;
        int r0 = __float_as_int(rp.x), r1 = __float_as_int(rp.y);
        float fy = rp.z, myy = rp.w;

        float gx = 1.0f - fx, gy = 1.0f - fy;
        float w00 = gy * gx, w01 = gy * fx, w10 = fy * gx, w11 = fy * fx;
        int o00 = r0 + xa, o01 = r0 + xb, o10 = r1 + xa, o11 = r1 + xb;

        float a = w00 * __ldg(c0 + o00) + w01 * __ldg(c0 + o01)
                + w10 * __ldg(c0 + o10) + w11 * __ldg(c0 + o11);
        float b = w00 * __ldg(c1 + o00) + w01 * __ldg(c1 + o01)
                + w10 * __ldg(c1 + o10) + w11 * __ldg(c1 + o11);

        // masked samples become exactly +0.0f (select, NOT multiply: 0*-x = -0,
        // and atan2(-0, b<0) = -pi would bin as 0 instead of reference's 4)
        bool valid = (mxx != 0.0f) && (myy != 0.0f);
        a = valid ? a : 0.0f;
        b = valid ? b : 0.0f;

        float r2 = fmaf(a, a, b * b);
        float mag = (r2 > 0.0f) ? r2 * rsqrtf(r2) : 0.0f;

        // bin = floor((atan2(a,b)+pi) * 8/(2*pi)), clipped to [0,7] => octant of (b,a)
        int bin;
        if (a > 0.0f) {
            if (b > 0.0f)      bin = (a < b)   ? 4 : 5;
            else if (b < 0.0f) bin = (a > -b)  ? 6 : 7;
            else               bin = 6;
        } else if (a < 0.0f) {
            if (b > 0.0f)      bin = (-a <= b) ? 3 : 2;
            else if (b < 0.0f) bin = (a > b)   ? 0 : 1;
            else               bin = 2;
        } else {
            bin = (b < 0.0f) ? 7 : 4;
        }

        msum[bin << 8] += mag;
        unsigned int inc = 1u << ((bin & 3) << 3);
        if (bin & 4) cnt1 += inc; else cnt0 += inc;
    }

    // unpack counts into smem once
#pragma unroll
    for (int b = 0; b < 4; b++) {
        hcnt[(b    ) * TPB + tid] = (float)((cnt0 >> (b << 3)) & 0xFFu);
        hcnt[(b + 4) * TPB + tid] = (float)((cnt1 >> (b << 3)) & 0xFFu);
    }
    __syncthreads();

    // 8 warps reduce 8 bins (warp w -> bin w), 256 partials each
    int wid = tid >> 5, lane = tid & 31;
    float s = 0.0f, c = 0.0f;
#pragma unroll
    for (int t = 0; t < TPB; t += 32) {
        s += hsum[(wid << 8) + lane + t];
        c += hcnt[(wid << 8) + lane + t];
    }
#pragma unroll
    for (int d = 16; d > 0; d >>= 1) {
        s += __shfl_down_sync(0xffffffffu, s, d);
        c += __shfl_down_sync(0xffffffffu, c, d);
    }
    if (lane == 0) {
        g_psum[bx * NBINS + wid] = s;
        g_pcnt[bx * NBINS + wid] = c;
    }
}

__global__ void vel_hist_finalize_kernel(float* __restrict__ out)
{
    int idx = blockIdx.x * blockDim.x + threadIdx.x;   // box*8 + bin
    if (idx >= NBOX * NBINS) return;
    int box = idx >> 3;
    int bin = idx & 7;
    float s = 0.0f, c = 0.0f;
#pragma unroll
    for (int p = 0; p < SPLIT; p++) {
        s += g_psum[(box * SPLIT + p) * NBINS + bin];
        c += g_pcnt[(box * SPLIT + p) * NBINS + bin];
    }
    out[idx] = (c != 0.0f) ? (s / c) : 0.0f;
}

extern "C" void kernel_launch(void* const* d_in, const int* in_sizes, int n_in,
                              void* d_out, int out_size) {
    const float* flows = (const float*)d_in[0];   // (8, 2, 512, 512) f32
    const float* boxes = (const float*)d_in[1];   // (512, 5) f32
    float* out = (float*)d_out;                   // (512, 8) f32
    vel_hist_part_kernel<<<NBOX * SPLIT, TPB>>>(flows, boxes);
    vel_hist_finalize_kernel<<<(NBOX * NBINS + 255) / 256, 256>>>(out);
}